// round 1
// baseline (speedup 1.0000x reference)
#include <cuda_runtime.h>
#include <math.h>

// Problem constants
constexpr int FH   = 96;          // feature map height (axis 1, "y")
constexpr int FW   = 96;          // feature map width  (axis 2, "x")
constexpr int FC   = 512;         // channels
constexpr int FB   = 16;          // batch
constexpr int NROI = 32;
constexpr int NREG = 50;          // 1 + 4 + 9 + 36
constexpr int C4   = FC / 4;      // float4 channels = 128

// Region table: per (roi, region) -> x1, x2, y1, y2
__device__ int4 d_regions[NROI * NREG];

// ---------------------------------------------------------------------------
// Kernel A: compute region boundaries with EXACT Python-double semantics.
//   cl = h / p   (governs x axis in the reference, quirk replicated)
//   rl = w / p   (governs y axis)
//   x1 = int(round(x + ix*cl)); x2 = int(round((x + ix*cl) + cl))
// round() is banker's rounding -> rint() in default RN mode.
// __dmul_rn/__dadd_rn prevent FMA contraction from perturbing .5 boundaries.
// ---------------------------------------------------------------------------
__global__ void compute_regions_kernel(const int* __restrict__ rois) {
    int r = blockIdx.x * blockDim.x + threadIdx.x;
    if (r >= NROI * NREG) return;

    int roi = r / NREG;
    int k   = r % NREG;

    int P, off;
    if      (k < 1)  { P = 1; off = 0; }
    else if (k < 5)  { P = 2; off = 1; }
    else if (k < 14) { P = 3; off = 5; }
    else             { P = 6; off = 14; }
    int idx = k - off;
    int ix  = idx / P;
    int jy  = idx % P;

    double x = (double)rois[roi * 4 + 0];
    double y = (double)rois[roi * 4 + 1];
    double w = (double)rois[roi * 4 + 2];
    double h = (double)rois[roi * 4 + 3];

    double cl = h / (double)P;   // x-axis step (reference quirk)
    double rl = w / (double)P;   // y-axis step

    double tx = __dadd_rn(x, __dmul_rn((double)ix, cl));
    int x1 = (int)rint(tx);
    int x2 = (int)rint(__dadd_rn(tx, cl));

    double ty = __dadd_rn(y, __dmul_rn((double)jy, rl));
    int y1 = (int)rint(ty);
    int y2 = (int)rint(__dadd_rn(ty, rl));

    // Safety clamps (reference data never exceeds bounds: x+h <= 94 < 96)
    x1 = max(0, min(FW, x1));
    x2 = max(0, min(FW, x2));
    y1 = max(0, min(FH, y1));
    y2 = max(0, min(FH, y2));

    d_regions[r] = make_int4(x1, x2, y1, y2);
}

__device__ __forceinline__ void vmax4(float4& a, const float4 b) {
    a.x = fmaxf(a.x, b.x);
    a.y = fmaxf(a.y, b.y);
    a.z = fmaxf(a.z, b.z);
    a.w = fmaxf(a.w, b.w);
}

// ---------------------------------------------------------------------------
// Per-pool compute: one (roi, pool, batch) per block; thread c owns 4 channels.
// Region (ix, jy): x-range depends only on ix, y-range only on jy.
// Scan each y band once, keep P accumulators (one per ix segment) in registers.
// ---------------------------------------------------------------------------
template <int P>
__device__ __forceinline__ void pool_compute(const float4* __restrict__ fmb,
                                             const int4*  __restrict__ regs,
                                             float4*      __restrict__ outb,
                                             int c) {
    int xs1[P], xs2[P], ys1[P], ys2[P];
#pragma unroll
    for (int i = 0; i < P; i++) {          // region (ix=i, jy=0) -> idx i*P
        int4 q = regs[i * P];
        xs1[i] = q.x; xs2[i] = q.y;
    }
#pragma unroll
    for (int j = 0; j < P; j++) {          // region (ix=0, jy=j) -> idx j
        int4 q = regs[j];
        ys1[j] = q.z; ys2[j] = q.w;
    }

#pragma unroll
    for (int j = 0; j < P; j++) {
        float4 acc[P];
#pragma unroll
        for (int i = 0; i < P; i++)
            acc[i] = make_float4(-INFINITY, -INFINITY, -INFINITY, -INFINITY);

        for (int y = ys1[j]; y < ys2[j]; y++) {
            const float4* row = fmb + (size_t)y * FW * C4 + c;
#pragma unroll
            for (int i = 0; i < P; i++) {
                int xe = xs2[i];
#pragma unroll 4
                for (int x = xs1[i]; x < xe; x++) {
                    float4 v = __ldg(row + (size_t)x * C4);
                    vmax4(acc[i], v);
                }
            }
        }
#pragma unroll
        for (int i = 0; i < P; i++)
            outb[(size_t)(i * P + j) * C4 + c] = acc[i];
    }
}

// Grid: NROI * 4 * FB blocks, roi-major so a ROI's 64 blocks co-run (L2 reuse).
__global__ void __launch_bounds__(128)
roi_pool_kernel(const float* __restrict__ fm, float* __restrict__ out) {
    int bid  = blockIdx.x;
    int roi  = bid >> 6;         // 64 blocks per roi
    int rem  = bid & 63;
    int pool = rem >> 4;         // 4 pools
    int b    = rem & 15;         // 16 batches
    int c    = threadIdx.x;      // float4-channel 0..127

    const float4* fmb  = (const float4*)fm + (size_t)b * FH * FW * C4;
    float4*       outb = (float4*)out + ((size_t)b * NROI * NREG + (size_t)roi * NREG) * C4;
    const int4*   regs = d_regions + roi * NREG;

    switch (pool) {
        case 0: pool_compute<1>(fmb, regs,      outb,                 c); break;
        case 1: pool_compute<2>(fmb, regs + 1,  outb + (size_t)1  * C4, c); break;
        case 2: pool_compute<3>(fmb, regs + 5,  outb + (size_t)5  * C4, c); break;
        default:pool_compute<6>(fmb, regs + 14, outb + (size_t)14 * C4, c); break;
    }
}

extern "C" void kernel_launch(void* const* d_in, const int* in_sizes, int n_in,
                              void* d_out, int out_size) {
    const float* fm   = (const float*)d_in[0];
    const int*   rois = (const int*)d_in[1];
    float*       out  = (float*)d_out;

    compute_regions_kernel<<<(NROI * NREG + 255) / 256, 256>>>(rois);
    roi_pool_kernel<<<NROI * 4 * FB, 128>>>(fm, out);
}